// round 1
// baseline (speedup 1.0000x reference)
#include <cuda_runtime.h>

#define N_TOK 16384
#define DIM   1024
#define NEXP  16
#define HID   4096

// Scratch (no device allocation allowed): per-expert token lists.
__device__ int   g_counts[NEXP];
__device__ int   g_perm [NEXP * N_TOK];
__device__ float g_gatev[NEXP * N_TOK];

__global__ void zero_counts_kernel() {
    if (threadIdx.x < NEXP) g_counts[threadIdx.x] = 0;
}

// Router: logits = x @ Wn + bn  ->  top-2 -> softmax -> bucket tokens per expert.
// Block: 256 threads handles 128 tokens x 16 experts. tx = expert, g = token group.
__global__ __launch_bounds__(256) void router_kernel(
    const float* __restrict__ x,
    const float* __restrict__ Wn,
    const float* __restrict__ bn,
    float* __restrict__ out)
{
    __shared__ float Xs[32][129];   // [d][token], padded
    __shared__ float Ws[32][16];    // [d][expert]

    const int tid  = threadIdx.x;
    const int tx   = tid & 15;      // expert
    const int g    = tid >> 4;      // token sub-group 0..15
    const int tok0 = blockIdx.x * 128;

    float acc[8];
#pragma unroll
    for (int i = 0; i < 8; i++) acc[i] = 0.f;

    for (int dk = 0; dk < DIM; dk += 32) {
#pragma unroll
        for (int p = 0; p < 4; p++) {
            int t  = (tid >> 3) + p * 32;
            int d4 = (tid & 7) * 4;
            float4 v = *(const float4*)(x + (size_t)(tok0 + t) * DIM + dk + d4);
            Xs[d4 + 0][t] = v.x;
            Xs[d4 + 1][t] = v.y;
            Xs[d4 + 2][t] = v.z;
            Xs[d4 + 3][t] = v.w;
        }
        {
            int idx = tid * 2;
            int d = idx >> 4, ee = idx & 15;
            float2 w = *(const float2*)(Wn + (size_t)(dk + d) * NEXP + ee);
            Ws[d][ee]     = w.x;
            Ws[d][ee + 1] = w.y;
        }
        __syncthreads();
#pragma unroll
        for (int kk = 0; kk < 32; kk++) {
            float wv = Ws[kk][tx];
#pragma unroll
            for (int i = 0; i < 8; i++)
                acc[i] += Xs[kk][g + 16 * i] * wv;
        }
        __syncthreads();
    }

    const float bb = bn[tx];
#pragma unroll
    for (int i = 0; i < 8; i++) {
        // top-2 over the 16 expert lanes of this half-warp (butterfly, width 16)
        float v0 = acc[i] + bb;
        int   i0 = tx;
        float v1 = -3.4e38f;
        int   i1 = NEXP;           // sentinel: never wins tie-break
#pragma unroll
        for (int off = 8; off >= 1; off >>= 1) {
            float ov0 = __shfl_xor_sync(0xffffffffu, v0, off);
            int   oi0 = __shfl_xor_sync(0xffffffffu, i0, off);
            float ov1 = __shfl_xor_sync(0xffffffffu, v1, off);
            int   oi1 = __shfl_xor_sync(0xffffffffu, i1, off);
            bool other_first = (ov0 > v0) || (ov0 == v0 && oi0 < i0);
            float n0, n1; int m0, m1;
            if (other_first) {
                n0 = ov0; m0 = oi0;
                if (v0 > ov1 || (v0 == ov1 && i0 < oi1)) { n1 = v0;  m1 = i0;  }
                else                                     { n1 = ov1; m1 = oi1; }
            } else {
                n0 = v0; m0 = i0;
                if (ov0 > v1 || (ov0 == v1 && oi0 < i1)) { n1 = ov0; m1 = oi0; }
                else                                     { n1 = v1;  m1 = i1;  }
            }
            v0 = n0; i0 = m0; v1 = n1; i1 = m1;
        }
        if (tx == 0) {
            int token = tok0 + g + 16 * i;
            // softmax over [v0, v1], v0 >= v1
            float e1  = __expf(v1 - v0);
            float inv = 1.f / (1.f + e1);
            float g0 = inv;
            float g1 = e1 * inv;
            int p0 = atomicAdd(&g_counts[i0], 1);
            g_perm [i0 * N_TOK + p0] = token;
            g_gatev[i0 * N_TOK + p0] = g0;
            int p1 = atomicAdd(&g_counts[i1], 1);
            g_perm [i1 * N_TOK + p1] = token;
            g_gatev[i1 * N_TOK + p1] = g1;
            out[token] = 0.f;
        }
    }
}

// Fused expert kernel: for expert e, gather a tile of 128 assigned tokens,
// compute h = relu(X @ W1[e] + b1[e]) 64 H-columns at a time, immediately
// contract with W2[e] (h never touches global), atomicAdd gated scalar to out.
// blockIdx.y = expert, blockIdx.x = token tile.
__global__ __launch_bounds__(256) void moe_kernel(
    const float* __restrict__ x,
    const float* __restrict__ W1,
    const float* __restrict__ b1,
    const float* __restrict__ W2,
    const float* __restrict__ b2,
    float* __restrict__ out)
{
    const int e     = blockIdx.y;
    const int cnt   = g_counts[e];
    const int tbase = blockIdx.x * 128;
    if (tbase >= cnt) return;

    __shared__ float Xs[32][132];   // [d][token], padded (stride 528B, 16B-aligned)
    __shared__ float Ws[32][64];    // [d][h]
    __shared__ float red[128][17];
    __shared__ int   toks[128];
    __shared__ float gts [128];

    const int tid = threadIdx.x;
    const int tx  = tid & 15;       // col group (4 h-cols)
    const int ty  = tid >> 4;       // row group (8 tokens)

    if (tid < 128) {
        int idx = tbase + tid;
        int t = 0; float gv = 0.f;
        if (idx < cnt) {
            t  = g_perm [e * N_TOK + idx];
            gv = g_gatev[e * N_TOK + idx];
        }
        toks[tid] = t;
        gts [tid] = gv;
    }
    __syncthreads();

    int myTok[4];
#pragma unroll
    for (int p = 0; p < 4; p++) myTok[p] = toks[(tid >> 3) + p * 32];

    float sacc[8];
#pragma unroll
    for (int i = 0; i < 8; i++) sacc[i] = 0.f;

    const float* W1e = W1 + (size_t)e * DIM * HID;

    for (int hc = 0; hc < HID; hc += 64) {
        float C[8][4];
#pragma unroll
        for (int i = 0; i < 8; i++)
#pragma unroll
            for (int j = 0; j < 4; j++) C[i][j] = 0.f;

        for (int dk = 0; dk < DIM; dk += 32) {
            // gather X tile [128 tok][32 d] transposed into smem
#pragma unroll
            for (int p = 0; p < 4; p++) {
                int t  = (tid >> 3) + p * 32;
                int d4 = (tid & 7) * 4;
                float4 v = *(const float4*)(x + (size_t)myTok[p] * DIM + dk + d4);
                Xs[d4 + 0][t] = v.x;
                Xs[d4 + 1][t] = v.y;
                Xs[d4 + 2][t] = v.z;
                Xs[d4 + 3][t] = v.w;
            }
            // W1 tile [32 d][64 h]
#pragma unroll
            for (int p = 0; p < 2; p++) {
                int fidx = tid + p * 256;
                int row  = fidx >> 4;
                int c4   = (fidx & 15) * 4;
                float4 w = *(const float4*)(W1e + (size_t)(dk + row) * HID + hc + c4);
                *(float4*)&Ws[row][c4] = w;
            }
            __syncthreads();
#pragma unroll
            for (int kk = 0; kk < 32; kk++) {
                float4 a0 = *(const float4*)&Xs[kk][ty * 8];
                float4 a1 = *(const float4*)&Xs[kk][ty * 8 + 4];
                float4 bf = *(const float4*)&Ws[kk][tx * 4];
                float av[8] = {a0.x, a0.y, a0.z, a0.w, a1.x, a1.y, a1.z, a1.w};
                float bv[4] = {bf.x, bf.y, bf.z, bf.w};
#pragma unroll
                for (int i = 0; i < 8; i++)
#pragma unroll
                    for (int j = 0; j < 4; j++)
                        C[i][j] += av[i] * bv[j];
            }
            __syncthreads();
        }

        // epilogue for this 64-wide H chunk: relu(+b1), dot with W2
        float4 bb = *(const float4*)(b1 + (size_t)e * HID + hc + tx * 4);
        float4 ww = *(const float4*)(W2 + (size_t)e * HID + hc + tx * 4);
        float bbv[4] = {bb.x, bb.y, bb.z, bb.w};
        float wwv[4] = {ww.x, ww.y, ww.z, ww.w};
#pragma unroll
        for (int i = 0; i < 8; i++) {
#pragma unroll
            for (int j = 0; j < 4; j++) {
                float v = C[i][j] + bbv[j];
                v = fmaxf(v, 0.f);
                sacc[i] += v * wwv[j];
            }
        }
    }

    // reduce sacc across the 16 tx lanes per token row, then write out
#pragma unroll
    for (int i = 0; i < 8; i++) red[ty * 8 + i][tx] = sacc[i];
    __syncthreads();
    if (tid < 128) {
        float s = 0.f;
#pragma unroll
        for (int c = 0; c < 16; c++) s += red[tid][c];
        int idx = tbase + tid;
        if (idx < cnt) {
            float contrib = gts[tid] * (s + b2[e]);
            atomicAdd(&out[toks[tid]], contrib);
        }
    }
}

extern "C" void kernel_launch(void* const* d_in, const int* in_sizes, int n_in,
                              void* d_out, int out_size) {
    // metadata order: x, Wr, br, Wn, bn, W1, b1, W2, b2, k
    const float* x  = (const float*)d_in[0];
    const float* Wn = (const float*)d_in[3];
    const float* bn = (const float*)d_in[4];
    const float* W1 = (const float*)d_in[5];
    const float* b1 = (const float*)d_in[6];
    const float* W2 = (const float*)d_in[7];
    const float* b2 = (const float*)d_in[8];
    float* out = (float*)d_out;

    zero_counts_kernel<<<1, 32>>>();
    router_kernel<<<N_TOK / 128, 256>>>(x, Wn, bn, out);
    moe_kernel<<<dim3(128, NEXP), 256>>>(x, W1, b1, W2, b2, out);
}

// round 3
// speedup vs baseline: 3.9771x; 3.9771x over previous
#include <cuda_runtime.h>
#include <cstdint>

#define N_TOK 16384
#define DIM   1024
#define NEXP  16
#define HID   4096

// ---------------- device scratch (no allocations allowed) ----------------
__device__ int   g_counts[NEXP];
__device__ int   g_perm [NEXP * N_TOK];
__device__ float g_gatev[NEXP * N_TOK];
__device__ float g_xr [(size_t)N_TOK * DIM];          // x rounded to tf32
__device__ float g_w1r[(size_t)NEXP * DIM * HID];     // W1 rounded to tf32

// ---------------- helpers ----------------
__device__ __forceinline__ uint32_t smem_u32(const void* p) {
    uint32_t a;
    asm("{ .reg .u64 t; cvta.to.shared.u64 t, %1; cvt.u32.u64 %0, t; }" : "=r"(a) : "l"(p));
    return a;
}
__device__ __forceinline__ float tf32r(float v) {
    uint32_t r;
    asm("cvt.rna.tf32.f32 %0, %1;" : "=r"(r) : "f"(v));
    return __uint_as_float(r);
}
#define CP_ASYNC16(dst, src) \
    asm volatile("cp.async.cg.shared.global [%0], [%1], 16;" :: "r"(dst), "l"(src) : "memory")
#define CP_COMMIT() asm volatile("cp.async.commit_group;" ::: "memory")
#define CP_WAIT(n)  asm volatile("cp.async.wait_group %0;" :: "n"(n) : "memory")

__device__ __forceinline__ void mma_tf32(float* c, const uint32_t* a, const uint32_t* b) {
    asm volatile(
        "mma.sync.aligned.m16n8k8.row.col.f32.tf32.tf32.f32 "
        "{%0,%1,%2,%3}, {%4,%5,%6,%7}, {%8,%9}, {%0,%1,%2,%3};"
        : "+f"(c[0]), "+f"(c[1]), "+f"(c[2]), "+f"(c[3])
        : "r"(a[0]), "r"(a[1]), "r"(a[2]), "r"(a[3]), "r"(b[0]), "r"(b[1]));
}

// ---------------- kernel 0: zero counts ----------------
__global__ void zero_counts_kernel() {
    if (threadIdx.x < NEXP) g_counts[threadIdx.x] = 0;
}

// ---------------- kernel 1: tf32-round a buffer (float4 grid-stride-free) ----
__global__ __launch_bounds__(256) void round_tf32_kernel(const float4* __restrict__ src,
                                                         float4* __restrict__ dst) {
    size_t i = (size_t)blockIdx.x * 256 + threadIdx.x;
    float4 v = src[i];
    v.x = tf32r(v.x); v.y = tf32r(v.y); v.z = tf32r(v.z); v.w = tf32r(v.w);
    dst[i] = v;
}

// ---------------- kernel 2: router (fp32 exact) ----------------
__global__ __launch_bounds__(256) void router_kernel(
    const float* __restrict__ x,
    const float* __restrict__ Wn,
    const float* __restrict__ bn,
    float* __restrict__ out)
{
    __shared__ float Xs[32][129];
    __shared__ float Ws[32][16];

    const int tid  = threadIdx.x;
    const int tx   = tid & 15;
    const int g    = tid >> 4;
    const int tok0 = blockIdx.x * 128;

    float acc[8];
#pragma unroll
    for (int i = 0; i < 8; i++) acc[i] = 0.f;

    for (int dk = 0; dk < DIM; dk += 32) {
#pragma unroll
        for (int p = 0; p < 4; p++) {
            int t  = (tid >> 3) + p * 32;
            int d4 = (tid & 7) * 4;
            float4 v = *(const float4*)(x + (size_t)(tok0 + t) * DIM + dk + d4);
            Xs[d4 + 0][t] = v.x;
            Xs[d4 + 1][t] = v.y;
            Xs[d4 + 2][t] = v.z;
            Xs[d4 + 3][t] = v.w;
        }
        {
            int idx = tid * 2;
            int d = idx >> 4, ee = idx & 15;
            float2 w = *(const float2*)(Wn + (size_t)(dk + d) * NEXP + ee);
            Ws[d][ee]     = w.x;
            Ws[d][ee + 1] = w.y;
        }
        __syncthreads();
#pragma unroll
        for (int kk = 0; kk < 32; kk++) {
            float wv = Ws[kk][tx];
#pragma unroll
            for (int i = 0; i < 8; i++)
                acc[i] += Xs[kk][g + 16 * i] * wv;
        }
        __syncthreads();
    }

    const float bb = bn[tx];
#pragma unroll
    for (int i = 0; i < 8; i++) {
        float v0 = acc[i] + bb;
        int   i0 = tx;
        float v1 = -3.4e38f;
        int   i1 = NEXP;
#pragma unroll
        for (int off = 8; off >= 1; off >>= 1) {
            float ov0 = __shfl_xor_sync(0xffffffffu, v0, off);
            int   oi0 = __shfl_xor_sync(0xffffffffu, i0, off);
            float ov1 = __shfl_xor_sync(0xffffffffu, v1, off);
            int   oi1 = __shfl_xor_sync(0xffffffffu, i1, off);
            bool other_first = (ov0 > v0) || (ov0 == v0 && oi0 < i0);
            float n0, n1; int m0, m1;
            if (other_first) {
                n0 = ov0; m0 = oi0;
                if (v0 > ov1 || (v0 == ov1 && i0 < oi1)) { n1 = v0;  m1 = i0;  }
                else                                     { n1 = ov1; m1 = oi1; }
            } else {
                n0 = v0; m0 = i0;
                if (ov0 > v1 || (ov0 == v1 && oi0 < i1)) { n1 = ov0; m1 = oi0; }
                else                                     { n1 = v1;  m1 = i1;  }
            }
            v0 = n0; i0 = m0; v1 = n1; i1 = m1;
        }
        if (tx == 0) {
            int token = tok0 + g + 16 * i;
            float e1  = __expf(v1 - v0);
            float inv = 1.f / (1.f + e1);
            int p0 = atomicAdd(&g_counts[i0], 1);
            g_perm [i0 * N_TOK + p0] = token;
            g_gatev[i0 * N_TOK + p0] = inv;
            int p1 = atomicAdd(&g_counts[i1], 1);
            g_perm [i1 * N_TOK + p1] = token;
            g_gatev[i1 * N_TOK + p1] = e1 * inv;
            out[token] = 0.f;
        }
    }
}

// ---------------- kernel 3: mma.sync tf32 expert GEMM + fused epilogue ----------
// CTA = (128-token tile, expert). 8 warps in 2x4 grid; warp tile 64x32.
// Loop: 32 H-chunks of 128 cols; per chunk, K=1024 in 64 steps of 16 (cp.async
// double-buffered), then fused relu(+b1)*W2 epilogue into per-thread sacc.
#define AS_STRIDE 20   /* 16 k-floats + 4 pad -> conflict-free A frags */
#define BS_STRIDE 136  /* 128 n-floats + 8 pad -> conflict-free B frags */

__global__ __launch_bounds__(256) void moe_mma_kernel(
    const float* __restrict__ b1,
    const float* __restrict__ W2,
    const float* __restrict__ b2,
    float* __restrict__ out)
{
    const int e     = blockIdx.y;
    const int cnt   = g_counts[e];
    const int tbase = blockIdx.x * 128;
    if (tbase >= cnt) return;

    __shared__ float As[2][128 * AS_STRIDE];
    __shared__ float Bs[2][16 * BS_STRIDE];
    __shared__ float b1s[128], w2s[128];
    __shared__ int   toks_s[128];
    __shared__ float gts_s[128];
    __shared__ float red_s[128][4];

    const int tid  = threadIdx.x;
    const int wid  = tid >> 5;
    const int lane = tid & 31;
    const int wy   = wid >> 2;       // 0..1  (m block of 64)
    const int wx   = wid & 3;        // 0..3  (n block of 32)
    const int r_   = lane >> 2;      // 0..7
    const int c_   = lane & 3;       // 0..3

    if (tid < 128) {
        int idx = tbase + tid;
        int t = 0; float gv = 0.f;
        if (idx < cnt) { t = g_perm[e * N_TOK + idx]; gv = g_gatev[e * N_TOK + idx]; }
        toks_s[tid] = t;
        gts_s[tid]  = gv;
    }
    __syncthreads();

    // ---- loader setup ----
    // A: each thread owns row (tid>>1), two 16B chunks (tid&1)*2 + {0,1}
    const float* a_src = g_xr + (size_t)toks_s[tid >> 1] * DIM + ((tid & 1) * 2) * 4;
    const uint32_t a_dst0 = smem_u32(&As[0][0]) + (uint32_t)(tid >> 1) * (AS_STRIDE * 4)
                          + (uint32_t)((tid & 1) * 2) * 16;
    const uint32_t a_buf_sz = 128 * AS_STRIDE * 4;
    // B: each thread owns d-row (tid>>4), two 16B chunks (tid&15)*2 + {0,1}
    const float* b_src = g_w1r + (size_t)e * DIM * HID + (size_t)(tid >> 4) * HID
                       + ((tid & 15) * 2) * 4;
    const uint32_t b_dst0 = smem_u32(&Bs[0][0]) + (uint32_t)(tid >> 4) * (BS_STRIDE * 4)
                          + (uint32_t)((tid & 15) * 2) * 16;
    const uint32_t b_buf_sz = 16 * BS_STRIDE * 4;

    float sacc[4][2];
#pragma unroll
    for (int mi = 0; mi < 4; mi++) { sacc[mi][0] = 0.f; sacc[mi][1] = 0.f; }

    const float* b1e = b1 + (size_t)e * HID;
    const float* w2e = W2 + (size_t)e * HID;

    for (int hc = 0; hc < HID / 128; hc++) {
        __syncthreads();   // previous epilogue finished reading b1s/w2s
        if (tid < 128) b1s[tid] = b1e[hc * 128 + tid];
        else           w2s[tid - 128] = w2e[hc * 128 + (tid - 128)];

        float C[4][4][4];
#pragma unroll
        for (int mi = 0; mi < 4; mi++)
#pragma unroll
            for (int ni = 0; ni < 4; ni++)
#pragma unroll
                for (int q = 0; q < 4; q++) C[mi][ni][q] = 0.f;

        // prologue: load k-tile 0 into buf 0
        {
            const float* as = a_src;                       // kt=0
            const float* bs = b_src + (size_t)hc * 128;
            CP_ASYNC16(a_dst0,      as);
            CP_ASYNC16(a_dst0 + 16, as + 4);
            CP_ASYNC16(b_dst0,      bs);
            CP_ASYNC16(b_dst0 + 16, bs + 4);
            CP_COMMIT();
        }

        for (int kt = 0; kt < 64; kt++) {
            __syncthreads();   // all warps done with buffer being overwritten next
            if (kt < 63) {
                const int nb = (kt + 1) & 1;
                const float* as = a_src + (kt + 1) * 16;
                const float* bs = b_src + (size_t)(kt + 1) * 16 * HID + (size_t)hc * 128;
                CP_ASYNC16(a_dst0 + nb * a_buf_sz,      as);
                CP_ASYNC16(a_dst0 + nb * a_buf_sz + 16, as + 4);
                CP_ASYNC16(b_dst0 + nb * b_buf_sz,      bs);
                CP_ASYNC16(b_dst0 + nb * b_buf_sz + 16, bs + 4);
                CP_COMMIT();
                CP_WAIT(1);
            } else {
                CP_WAIT(0);
            }
            __syncthreads();

            const int buf = kt & 1;
            const float* Ab = &As[buf][0];
            const float* Bb = &Bs[buf][0];
#pragma unroll
            for (int s = 0; s < 2; s++) {
                const int k0 = s * 8;
                uint32_t af[4][4];
#pragma unroll
                for (int mi = 0; mi < 4; mi++) {
                    const float* p = Ab + (wy * 64 + mi * 16 + r_) * AS_STRIDE + k0 + c_;
                    af[mi][0] = __float_as_uint(p[0]);
                    af[mi][1] = __float_as_uint(p[8 * AS_STRIDE]);
                    af[mi][2] = __float_as_uint(p[4]);
                    af[mi][3] = __float_as_uint(p[8 * AS_STRIDE + 4]);
                }
                uint32_t bf[4][2];
#pragma unroll
                for (int ni = 0; ni < 4; ni++) {
                    const float* q = Bb + (k0 + c_) * BS_STRIDE + wx * 32 + ni * 8 + r_;
                    bf[ni][0] = __float_as_uint(q[0]);
                    bf[ni][1] = __float_as_uint(q[4 * BS_STRIDE]);
                }
#pragma unroll
                for (int mi = 0; mi < 4; mi++)
#pragma unroll
                    for (int ni = 0; ni < 4; ni++)
                        mma_tf32(C[mi][ni], af[mi], bf[ni]);
            }
        }

        // fused epilogue for this 128-wide H chunk
#pragma unroll
        for (int mi = 0; mi < 4; mi++) {
#pragma unroll
            for (int ni = 0; ni < 4; ni++) {
                const int wn0 = wx * 32 + ni * 8 + 2 * c_;
                float2 bb = *(const float2*)&b1s[wn0];
                float2 ww = *(const float2*)&w2s[wn0];
                sacc[mi][0] += fmaxf(C[mi][ni][0] + bb.x, 0.f) * ww.x
                             + fmaxf(C[mi][ni][1] + bb.y, 0.f) * ww.y;
                sacc[mi][1] += fmaxf(C[mi][ni][2] + bb.x, 0.f) * ww.x
                             + fmaxf(C[mi][ni][3] + bb.y, 0.f) * ww.y;
            }
        }
    }

    // ---- final reduction: fold the 4 c-lanes, then the 4 warp columns ----
#pragma unroll
    for (int mi = 0; mi < 4; mi++)
#pragma unroll
        for (int j = 0; j < 2; j++) {
            float v = sacc[mi][j];
            v += __shfl_xor_sync(0xffffffffu, v, 1);
            v += __shfl_xor_sync(0xffffffffu, v, 2);
            sacc[mi][j] = v;
        }
    if (c_ == 0) {
#pragma unroll
        for (int mi = 0; mi < 4; mi++) {
            red_s[wy * 64 + mi * 16 + r_][wx]     = sacc[mi][0];
            red_s[wy * 64 + mi * 16 + r_ + 8][wx] = sacc[mi][1];
        }
    }
    __syncthreads();

    if (tid < 128) {
        float tot = red_s[tid][0] + red_s[tid][1] + red_s[tid][2] + red_s[tid][3];
        int idx = tbase + tid;
        if (idx < cnt)
            atomicAdd(out + toks_s[tid], gts_s[tid] * (tot + b2[e]));
    }
}

// ---------------- launch ----------------
extern "C" void kernel_launch(void* const* d_in, const int* in_sizes, int n_in,
                              void* d_out, int out_size) {
    const float* x  = (const float*)d_in[0];
    const float* Wn = (const float*)d_in[3];
    const float* bn = (const float*)d_in[4];
    const float* W1 = (const float*)d_in[5];
    const float* b1 = (const float*)d_in[6];
    const float* W2 = (const float*)d_in[7];
    const float* b2 = (const float*)d_in[8];
    float* out = (float*)d_out;

    float* xr;  cudaGetSymbolAddress((void**)&xr,  g_xr);
    float* w1r; cudaGetSymbolAddress((void**)&w1r, g_w1r);

    zero_counts_kernel<<<1, 32>>>();
    router_kernel<<<N_TOK / 128, 256>>>(x, Wn, bn, out);
    round_tf32_kernel<<<(N_TOK * DIM / 4) / 256, 256>>>((const float4*)x, (float4*)xr);
    round_tf32_kernel<<<((size_t)NEXP * DIM * HID / 4) / 256, 256>>>((const float4*)W1, (float4*)w1r);
    moe_mma_kernel<<<dim3(128, NEXP), 256>>>(b1, W2, b2, out);
}

// round 5
// speedup vs baseline: 4.3561x; 1.0953x over previous
#include <cuda_runtime.h>
#include <cstdint>

#define N_TOK 16384
#define DIM   1024
#define NEXP  16
#define HID   4096

// ---------------- device scratch (no allocations allowed) ----------------
__device__ int   g_counts[NEXP];
__device__ int   g_perm [NEXP * N_TOK];
__device__ float g_gatev[NEXP * N_TOK];
__device__ float g_xr [(size_t)N_TOK * DIM];          // x rounded to tf32 (rna)
__device__ float g_w1r[(size_t)NEXP * DIM * HID];     // W1 rounded to tf32 (rna)

// ---------------- helpers ----------------
__device__ __forceinline__ uint32_t smem_u32(const void* p) {
    uint32_t a;
    asm("{ .reg .u64 t; cvta.to.shared.u64 t, %1; cvt.u32.u64 %0, t; }" : "=r"(a) : "l"(p));
    return a;
}
__device__ __forceinline__ float tf32r(float v) {
    uint32_t r;
    asm("cvt.rna.tf32.f32 %0, %1;" : "=r"(r) : "f"(v));
    return __uint_as_float(r);
}
#define CP_ASYNC16(dst, src) \
    asm volatile("cp.async.cg.shared.global [%0], [%1], 16;" :: "r"(dst), "l"(src) : "memory")
#define CP_COMMIT() asm volatile("cp.async.commit_group;" ::: "memory")
#define CP_WAIT(n)  asm volatile("cp.async.wait_group %0;" :: "n"(n) : "memory")

__device__ __forceinline__ void mma_tf32(float* c, const uint32_t* a, const uint32_t* b) {
    asm volatile(
        "mma.sync.aligned.m16n8k8.row.col.f32.tf32.tf32.f32 "
        "{%0,%1,%2,%3}, {%4,%5,%6,%7}, {%8,%9}, {%0,%1,%2,%3};"
        : "+f"(c[0]), "+f"(c[1]), "+f"(c[2]), "+f"(c[3])
        : "r"(a[0]), "r"(a[1]), "r"(a[2]), "r"(a[3]), "r"(b[0]), "r"(b[1]));
}

// ---------------- kernel 0: zero counts ----------------
__global__ void zero_counts_kernel() {
    if (threadIdx.x < NEXP) g_counts[threadIdx.x] = 0;
}

// ---------------- kernel 1: tf32-round a buffer ----------------
__global__ __launch_bounds__(256) void round_tf32_kernel(const float4* __restrict__ src,
                                                         float4* __restrict__ dst) {
    size_t i = (size_t)blockIdx.x * 256 + threadIdx.x;
    float4 v = src[i];
    v.x = tf32r(v.x); v.y = tf32r(v.y); v.z = tf32r(v.z); v.w = tf32r(v.w);
    dst[i] = v;
}

// ---------------- kernel 2: router (fp32 exact) ----------------
__global__ __launch_bounds__(256) void router_kernel(
    const float* __restrict__ x,
    const float* __restrict__ Wn,
    const float* __restrict__ bn,
    float* __restrict__ out)
{
    __shared__ float Xs[32][129];
    __shared__ float Ws[32][16];

    const int tid  = threadIdx.x;
    const int tx   = tid & 15;
    const int g    = tid >> 4;
    const int tok0 = blockIdx.x * 128;

    float acc[8];
#pragma unroll
    for (int i = 0; i < 8; i++) acc[i] = 0.f;

    for (int dk = 0; dk < DIM; dk += 32) {
#pragma unroll
        for (int p = 0; p < 4; p++) {
            int t  = (tid >> 3) + p * 32;
            int d4 = (tid & 7) * 4;
            float4 v = *(const float4*)(x + (size_t)(tok0 + t) * DIM + dk + d4);
            Xs[d4 + 0][t] = v.x;
            Xs[d4 + 1][t] = v.y;
            Xs[d4 + 2][t] = v.z;
            Xs[d4 + 3][t] = v.w;
        }
        {
            int idx = tid * 2;
            int d = idx >> 4, ee = idx & 15;
            float2 w = *(const float2*)(Wn + (size_t)(dk + d) * NEXP + ee);
            Ws[d][ee]     = w.x;
            Ws[d][ee + 1] = w.y;
        }
        __syncthreads();
#pragma unroll
        for (int kk = 0; kk < 32; kk++) {
            float wv = Ws[kk][tx];
#pragma unroll
            for (int i = 0; i < 8; i++)
                acc[i] += Xs[kk][g + 16 * i] * wv;
        }
        __syncthreads();
    }

    const float bb = bn[tx];
#pragma unroll
    for (int i = 0; i < 8; i++) {
        float v0 = acc[i] + bb;
        int   i0 = tx;
        float v1 = -3.4e38f;
        int   i1 = NEXP;
#pragma unroll
        for (int off = 8; off >= 1; off >>= 1) {
            float ov0 = __shfl_xor_sync(0xffffffffu, v0, off);
            int   oi0 = __shfl_xor_sync(0xffffffffu, i0, off);
            float ov1 = __shfl_xor_sync(0xffffffffu, v1, off);
            int   oi1 = __shfl_xor_sync(0xffffffffu, i1, off);
            bool other_first = (ov0 > v0) || (ov0 == v0 && oi0 < i0);
            float n0, n1; int m0, m1;
            if (other_first) {
                n0 = ov0; m0 = oi0;
                if (v0 > ov1 || (v0 == ov1 && i0 < oi1)) { n1 = v0;  m1 = i0;  }
                else                                     { n1 = ov1; m1 = oi1; }
            } else {
                n0 = v0; m0 = i0;
                if (ov0 > v1 || (ov0 == v1 && oi0 < i1)) { n1 = ov0; m1 = oi0; }
                else                                     { n1 = v1;  m1 = i1;  }
            }
            v0 = n0; i0 = m0; v1 = n1; i1 = m1;
        }
        if (tx == 0) {
            int token = tok0 + g + 16 * i;
            float e1  = __expf(v1 - v0);
            float inv = 1.f / (1.f + e1);
            int p0 = atomicAdd(&g_counts[i0], 1);
            g_perm [i0 * N_TOK + p0] = token;
            g_gatev[i0 * N_TOK + p0] = inv;
            int p1 = atomicAdd(&g_counts[i1], 1);
            g_perm [i1 * N_TOK + p1] = token;
            g_gatev[i1 * N_TOK + p1] = e1 * inv;
            out[token] = 0.f;
        }
    }
}

// ---------------- kernel 3: mma.sync tf32 expert GEMM, H-sliced ----------------
// CTA = (128-token tile, expert, H-slice of 512). 8 warps 2x4, warp tile 64x64.
// Flattened loop of 128 iters = 2 H-chunks(256) x 64 K-steps(16), 3-stage
// cp.async pipeline, ONE __syncthreads per iter. Fused relu(+b1)*W2 epilogue.
#define AS_STRIDE 20            // 16 k + 4 pad floats
#define BS_STRIDE 264           // 256 n + 8 pad floats
#define A_TILE_F  (128 * AS_STRIDE)   // floats per A buffer
#define B_TILE_F  (16 * BS_STRIDE)    // floats per B buffer
#define SM_B1_OFF   (3 * A_TILE_F + 3 * B_TILE_F)           // 20352
#define SM_W2_OFF   (SM_B1_OFF + 512)
#define SM_TOK_OFF  (SM_W2_OFF + 512)
#define SM_GTS_OFF  (SM_TOK_OFF + 128)
#define SM_RED_OFF  (SM_GTS_OFF + 128)
#define SM_TOTAL_F  (SM_RED_OFF + 512)
#define MOE_SMEM_BYTES (SM_TOTAL_F * 4)

__global__ __launch_bounds__(256, 1) void moe_mma_kernel(
    const float* __restrict__ b1,
    const float* __restrict__ W2,
    const float* __restrict__ b2,
    float* __restrict__ out)
{
    const int e     = blockIdx.y;
    const int cnt   = g_counts[e];
    const int tbase = blockIdx.x * 128;
    if (tbase >= cnt) return;
    const int slice = blockIdx.z;           // 0..7, 512 H cols each

    extern __shared__ float sm[];
    float* As     = sm;
    float* Bs     = sm + 3 * A_TILE_F;
    float* b1s    = sm + SM_B1_OFF;
    float* w2s    = sm + SM_W2_OFF;
    int*   toks_s = (int*)(sm + SM_TOK_OFF);
    float* gts_s  = sm + SM_GTS_OFF;
    float* red_s  = sm + SM_RED_OFF;        // [128][4]

    const int tid  = threadIdx.x;
    const int wid  = tid >> 5;
    const int lane = tid & 31;
    const int wy   = wid >> 2;              // 0..1 (m block 64)
    const int wx   = wid & 3;               // 0..3 (n block 64)
    const int r_   = lane >> 2;             // 0..7
    const int c_   = lane & 3;              // 0..3

    const int nbase = slice * 512;
    if (tid < 128) {
        int idx = tbase + tid;
        int t = 0; float gv = 0.f;
        if (idx < cnt) { t = g_perm[e * N_TOK + idx]; gv = g_gatev[e * N_TOK + idx]; }
        toks_s[tid] = t;
        gts_s[tid]  = gv;
    }
    // b1/W2 for the whole slice (512 each)
    {
        const float* b1e = b1 + (size_t)e * HID + nbase;
        const float* w2e = W2 + (size_t)e * HID + nbase;
        b1s[tid]       = b1e[tid];
        b1s[tid + 256] = b1e[tid + 256];
        w2s[tid]       = w2e[tid];
        w2s[tid + 256] = w2e[tid + 256];
    }
    __syncthreads();

    // ---- loader setup ----
    // A: thread owns token row (tid>>1), 8 floats at col (tid&1)*8 (2x 16B)
    const float* a_src = g_xr + (size_t)toks_s[tid >> 1] * DIM + (tid & 1) * 8;
    const uint32_t a_dst0 = smem_u32(As) + (uint32_t)(tid >> 1) * (AS_STRIDE * 4)
                          + (uint32_t)(tid & 1) * 32;
    // B: thread owns d-row (tid>>4), 16 floats at n (tid&15)*16 (4x 16B)
    const float* b_src = g_w1r + (size_t)e * DIM * HID + (size_t)(tid >> 4) * HID
                       + nbase + (tid & 15) * 16;
    const uint32_t b_dst0 = smem_u32(Bs) + (uint32_t)(tid >> 4) * (BS_STRIDE * 4)
                          + (uint32_t)(tid & 15) * 64;

    float sacc[4][2];
#pragma unroll
    for (int mi = 0; mi < 4; mi++) { sacc[mi][0] = 0.f; sacc[mi][1] = 0.f; }

    float C[4][8][4];
#pragma unroll
    for (int mi = 0; mi < 4; mi++)
#pragma unroll
        for (int ni = 0; ni < 8; ni++)
#pragma unroll
            for (int q = 0; q < 4; q++) C[mi][ni][q] = 0.f;

    // tile j: hc = j>>6 (H-chunk of 256), kt = j&63 (d-step of 16), buf j%3
#define LOAD_TILE(j) do {                                                        \
        const int   _kt = (j) & 63;                                              \
        const int   _hc = (j) >> 6;                                              \
        const int   _bf = (j) % 3;                                               \
        const float* _as = a_src + _kt * 16;                                     \
        const float* _bs = b_src + (size_t)_kt * (16 * HID) + _hc * 256;         \
        uint32_t _ad = a_dst0 + (uint32_t)_bf * (A_TILE_F * 4);                  \
        uint32_t _bd = b_dst0 + (uint32_t)_bf * (B_TILE_F * 4);                  \
        CP_ASYNC16(_ad,      _as);                                               \
        CP_ASYNC16(_ad + 16, _as + 4);                                           \
        CP_ASYNC16(_bd,      _bs);                                               \
        CP_ASYNC16(_bd + 16, _bs + 4);                                           \
        CP_ASYNC16(_bd + 32, _bs + 8);                                           \
        CP_ASYNC16(_bd + 48, _bs + 12);                                          \
    } while (0)

    LOAD_TILE(0); CP_COMMIT();
    LOAD_TILE(1); CP_COMMIT();

    for (int it = 0; it < 128; it++) {
        CP_WAIT(1);
        __syncthreads();
        if (it < 126) LOAD_TILE(it + 2);
        CP_COMMIT();

        const float* Ab = As + (it % 3) * A_TILE_F;
        const float* Bb = Bs + (it % 3) * B_TILE_F;
#pragma unroll
        for (int s = 0; s < 2; s++) {
            const int k0 = s * 8;
            uint32_t af[4][4];
#pragma unroll
            for (int mi = 0; mi < 4; mi++) {
                const float* p = Ab + (wy * 64 + mi * 16 + r_) * AS_STRIDE + k0 + c_;
                af[mi][0] = __float_as_uint(p[0]);
                af[mi][1] = __float_as_uint(p[8 * AS_STRIDE]);
                af[mi][2] = __float_as_uint(p[4]);
                af[mi][3] = __float_as_uint(p[8 * AS_STRIDE + 4]);
            }
            uint32_t bf[8][2];
#pragma unroll
            for (int ni = 0; ni < 8; ni++) {
                const float* q = Bb + (k0 + c_) * BS_STRIDE + wx * 64 + ni * 8 + r_;
                bf[ni][0] = __float_as_uint(q[0]);
                bf[ni][1] = __float_as_uint(q[4 * BS_STRIDE]);
            }
#pragma unroll
            for (int mi = 0; mi < 4; mi++)
#pragma unroll
                for (int ni = 0; ni < 8; ni++)
                    mma_tf32(C[mi][ni], af[mi], bf[ni]);
        }

        if ((it & 63) == 63) {
            // fused epilogue for H-chunk (it>>6): relu(+b1) dot W2, then reset C
            const int hb = (it >> 6) * 256;
#pragma unroll
            for (int mi = 0; mi < 4; mi++) {
#pragma unroll
                for (int ni = 0; ni < 8; ni++) {
                    const int nl = hb + wx * 64 + ni * 8 + 2 * c_;
                    float2 bb = *(const float2*)&b1s[nl];
                    float2 ww = *(const float2*)&w2s[nl];
                    sacc[mi][0] += fmaxf(C[mi][ni][0] + bb.x, 0.f) * ww.x
                                 + fmaxf(C[mi][ni][1] + bb.y, 0.f) * ww.y;
                    sacc[mi][1] += fmaxf(C[mi][ni][2] + bb.x, 0.f) * ww.x
                                 + fmaxf(C[mi][ni][3] + bb.y, 0.f) * ww.y;
                    C[mi][ni][0] = 0.f; C[mi][ni][1] = 0.f;
                    C[mi][ni][2] = 0.f; C[mi][ni][3] = 0.f;
                }
            }
        }
    }

    // ---- reduce: fold 4 c-lanes (shfl), then 4 warp columns (smem) ----
#pragma unroll
    for (int mi = 0; mi < 4; mi++)
#pragma unroll
        for (int j = 0; j < 2; j++) {
            float v = sacc[mi][j];
            v += __shfl_xor_sync(0xffffffffu, v, 1);
            v += __shfl_xor_sync(0xffffffffu, v, 2);
            sacc[mi][j] = v;
        }
    __syncthreads();
    if (c_ == 0) {
#pragma unroll
        for (int mi = 0; mi < 4; mi++) {
            red_s[(wy * 64 + mi * 16 + r_) * 4 + wx]     = sacc[mi][0];
            red_s[(wy * 64 + mi * 16 + r_ + 8) * 4 + wx] = sacc[mi][1];
        }
    }
    __syncthreads();

    if (tid < 128) {
        float tot = red_s[tid * 4] + red_s[tid * 4 + 1]
                  + red_s[tid * 4 + 2] + red_s[tid * 4 + 3];
        int idx = tbase + tid;
        if (idx < cnt) {
            if (slice == 0) tot += b2[e];
            atomicAdd(out + toks_s[tid], gts_s[tid] * tot);
        }
    }
}

// ---------------- launch ----------------
extern "C" void kernel_launch(void* const* d_in, const int* in_sizes, int n_in,
                              void* d_out, int out_size) {
    const float* x  = (const float*)d_in[0];
    const float* Wn = (const float*)d_in[3];
    const float* bn = (const float*)d_in[4];
    const float* W1 = (const float*)d_in[5];
    const float* b1 = (const float*)d_in[6];
    const float* W2 = (const float*)d_in[7];
    const float* b2 = (const float*)d_in[8];
    float* out = (float*)d_out;

    float* xr;  cudaGetSymbolAddress((void**)&xr,  g_xr);
    float* w1r; cudaGetSymbolAddress((void**)&w1r, g_w1r);

    cudaFuncSetAttribute(moe_mma_kernel,
                         cudaFuncAttributeMaxDynamicSharedMemorySize, MOE_SMEM_BYTES);

    zero_counts_kernel<<<1, 32>>>();
    router_kernel<<<N_TOK / 128, 256>>>(x, Wn, bn, out);
    round_tf32_kernel<<<(N_TOK * DIM / 4) / 256, 256>>>((const float4*)x, (float4*)xr);
    round_tf32_kernel<<<((size_t)NEXP * DIM * HID / 4) / 256, 256>>>((const float4*)W1, (float4*)w1r);
    moe_mma_kernel<<<dim3(128, NEXP, 8), 256, MOE_SMEM_BYTES>>>(b1, W2, b2, out);
}

// round 6
// speedup vs baseline: 9.3020x; 2.1354x over previous
#include <cuda_runtime.h>
#include <cuda_fp16.h>
#include <cstdint>

#define N_TOK 16384
#define DIM   1024
#define NEXP  16
#define HID   4096

// ---------------- device scratch (no allocations allowed) ----------------
__device__ int    g_counts[NEXP];
__device__ int    g_perm [NEXP * N_TOK];
__device__ float  g_gatev[NEXP * N_TOK];
__device__ __half g_xh [(size_t)N_TOK * DIM];          // x  rounded to fp16
__device__ __half g_w1h[(size_t)NEXP * DIM * HID];     // W1 rounded to fp16

// ---------------- helpers ----------------
__device__ __forceinline__ uint32_t smem_u32(const void* p) {
    uint32_t a;
    asm("{ .reg .u64 t; cvta.to.shared.u64 t, %1; cvt.u32.u64 %0, t; }" : "=r"(a) : "l"(p));
    return a;
}
#define CP_ASYNC16(dst, src) \
    asm volatile("cp.async.cg.shared.global [%0], [%1], 16;" :: "r"(dst), "l"(src) : "memory")
#define CP_COMMIT() asm volatile("cp.async.commit_group;" ::: "memory")
#define CP_WAIT(n)  asm volatile("cp.async.wait_group %0;" :: "n"(n) : "memory")

#define LDSM4(r, a) \
    asm volatile("ldmatrix.sync.aligned.m8n8.x4.shared.b16 {%0,%1,%2,%3}, [%4];" \
        : "=r"((r)[0]), "=r"((r)[1]), "=r"((r)[2]), "=r"((r)[3]) : "r"(a))
#define LDSM4T(r, a) \
    asm volatile("ldmatrix.sync.aligned.m8n8.x4.trans.shared.b16 {%0,%1,%2,%3}, [%4];" \
        : "=r"((r)[0]), "=r"((r)[1]), "=r"((r)[2]), "=r"((r)[3]) : "r"(a))

__device__ __forceinline__ void mma_f16(float* c, const uint32_t* a, const uint32_t* b) {
    asm volatile(
        "mma.sync.aligned.m16n8k16.row.col.f32.f16.f16.f32 "
        "{%0,%1,%2,%3}, {%4,%5,%6,%7}, {%8,%9}, {%0,%1,%2,%3};"
        : "+f"(c[0]), "+f"(c[1]), "+f"(c[2]), "+f"(c[3])
        : "r"(a[0]), "r"(a[1]), "r"(a[2]), "r"(a[3]), "r"(b[0]), "r"(b[1]));
}

// ---------------- kernel 0: zero counts ----------------
__global__ void zero_counts_kernel() {
    if (threadIdx.x < NEXP) g_counts[threadIdx.x] = 0;
}

// ---------------- kernel 1: fp16-round a buffer ----------------
__global__ __launch_bounds__(256) void to_half_kernel(const float4* __restrict__ src,
                                                      __half2* __restrict__ dst) {
    size_t i = (size_t)blockIdx.x * 256 + threadIdx.x;
    float4 v = src[i];
    dst[2 * i]     = __floats2half2_rn(v.x, v.y);
    dst[2 * i + 1] = __floats2half2_rn(v.z, v.w);
}

// ---------------- kernel 2: router (fp32 exact) ----------------
__global__ __launch_bounds__(256) void router_kernel(
    const float* __restrict__ x,
    const float* __restrict__ Wn,
    const float* __restrict__ bn,
    float* __restrict__ out)
{
    __shared__ float Xs[32][129];
    __shared__ float Ws[32][16];

    const int tid  = threadIdx.x;
    const int tx   = tid & 15;
    const int g    = tid >> 4;
    const int tok0 = blockIdx.x * 128;

    float acc[8];
#pragma unroll
    for (int i = 0; i < 8; i++) acc[i] = 0.f;

    for (int dk = 0; dk < DIM; dk += 32) {
#pragma unroll
        for (int p = 0; p < 4; p++) {
            int t  = (tid >> 3) + p * 32;
            int d4 = (tid & 7) * 4;
            float4 v = *(const float4*)(x + (size_t)(tok0 + t) * DIM + dk + d4);
            Xs[d4 + 0][t] = v.x;
            Xs[d4 + 1][t] = v.y;
            Xs[d4 + 2][t] = v.z;
            Xs[d4 + 3][t] = v.w;
        }
        {
            int idx = tid * 2;
            int d = idx >> 4, ee = idx & 15;
            float2 w = *(const float2*)(Wn + (size_t)(dk + d) * NEXP + ee);
            Ws[d][ee]     = w.x;
            Ws[d][ee + 1] = w.y;
        }
        __syncthreads();
#pragma unroll
        for (int kk = 0; kk < 32; kk++) {
            float wv = Ws[kk][tx];
#pragma unroll
            for (int i = 0; i < 8; i++)
                acc[i] += Xs[kk][g + 16 * i] * wv;
        }
        __syncthreads();
    }

    const float bb = bn[tx];
#pragma unroll
    for (int i = 0; i < 8; i++) {
        float v0 = acc[i] + bb;
        int   i0 = tx;
        float v1 = -3.4e38f;
        int   i1 = NEXP;
#pragma unroll
        for (int off = 8; off >= 1; off >>= 1) {
            float ov0 = __shfl_xor_sync(0xffffffffu, v0, off);
            int   oi0 = __shfl_xor_sync(0xffffffffu, i0, off);
            float ov1 = __shfl_xor_sync(0xffffffffu, v1, off);
            int   oi1 = __shfl_xor_sync(0xffffffffu, i1, off);
            bool other_first = (ov0 > v0) || (ov0 == v0 && oi0 < i0);
            float n0, n1; int m0, m1;
            if (other_first) {
                n0 = ov0; m0 = oi0;
                if (v0 > ov1 || (v0 == ov1 && i0 < oi1)) { n1 = v0;  m1 = i0;  }
                else                                     { n1 = ov1; m1 = oi1; }
            } else {
                n0 = v0; m0 = i0;
                if (ov0 > v1 || (ov0 == v1 && oi0 < i1)) { n1 = ov0; m1 = oi0; }
                else                                     { n1 = v1;  m1 = i1;  }
            }
            v0 = n0; i0 = m0; v1 = n1; i1 = m1;
        }
        if (tx == 0) {
            int token = tok0 + g + 16 * i;
            float e1  = __expf(v1 - v0);
            float inv = 1.f / (1.f + e1);
            int p0 = atomicAdd(&g_counts[i0], 1);
            g_perm [i0 * N_TOK + p0] = token;
            g_gatev[i0 * N_TOK + p0] = inv;
            int p1 = atomicAdd(&g_counts[i1], 1);
            g_perm [i1 * N_TOK + p1] = token;
            g_gatev[i1 * N_TOK + p1] = e1 * inv;
            out[token] = 0.f;
        }
    }
}

// ---------------- kernel 3: fp16 mma expert GEMM, H-sliced ----------------
// CTA = (128-token tile, expert, H-slice of 512). 8 warps 2x4, warp tile 64x64.
// 64 iters = 2 H-chunks(256) x 32 K-steps(32). 3-stage cp.async pipeline,
// one __syncthreads per iter. ldmatrix fragment loads. Fused relu(+b1)*W2.
#define AS_H 40                 // A smem row stride in halfs (32 + 8 pad)
#define BS_H 264                // B smem row stride in halfs (256 + 8 pad)
#define A_TILE_B (128 * AS_H * 2)     // 10240 bytes per A buffer
#define B_TILE_B (32 * BS_H * 2)      // 16896 bytes per B buffer
#define SM_B1_B   (3 * A_TILE_B + 3 * B_TILE_B)   // 81408
#define SM_W2_B   (SM_B1_B + 2048)
#define SM_TOK_B  (SM_W2_B + 2048)
#define SM_GTS_B  (SM_TOK_B + 512)
#define SM_RED_B  (SM_GTS_B + 512)
#define MOE_SMEM_BYTES (SM_RED_B + 2048)

__global__ __launch_bounds__(256, 1) void moe_mma_kernel(
    const float* __restrict__ b1,
    const float* __restrict__ W2,
    const float* __restrict__ b2,
    float* __restrict__ out)
{
    const int e     = blockIdx.y;
    const int cnt   = g_counts[e];
    const int tbase = blockIdx.x * 128;
    if (tbase >= cnt) return;
    const int slice = blockIdx.z;           // 0..7, 512 H cols each

    extern __shared__ char sm[];
    __half* As    = (__half*)sm;
    __half* Bs    = (__half*)(sm + 3 * A_TILE_B);
    float* b1s    = (float*)(sm + SM_B1_B);
    float* w2s    = (float*)(sm + SM_W2_B);
    int*   toks_s = (int*)  (sm + SM_TOK_B);
    float* gts_s  = (float*)(sm + SM_GTS_B);
    float* red_s  = (float*)(sm + SM_RED_B);   // [128][4]

    const int tid  = threadIdx.x;
    const int wid  = tid >> 5;
    const int lane = tid & 31;
    const int wy   = wid >> 2;              // 0..1 (m block 64)
    const int wx   = wid & 3;               // 0..3 (n block 64)
    const int r_   = lane >> 2;             // 0..7
    const int c_   = lane & 3;              // 0..3

    const int nbase = slice * 512;
    if (tid < 128) {
        int idx = tbase + tid;
        int t = 0; float gv = 0.f;
        if (idx < cnt) { t = g_perm[e * N_TOK + idx]; gv = g_gatev[e * N_TOK + idx]; }
        toks_s[tid] = t;
        gts_s[tid]  = gv;
    }
    {
        const float* b1e = b1 + (size_t)e * HID + nbase;
        const float* w2e = W2 + (size_t)e * HID + nbase;
        b1s[tid]       = b1e[tid];
        b1s[tid + 256] = b1e[tid + 256];
        w2s[tid]       = w2e[tid];
        w2s[tid + 256] = w2e[tid + 256];
    }
    __syncthreads();

    // ---- cp.async loader setup ----
    // A: thread owns token row (tid>>1), 16 halfs at (tid&1)*16 (2x 16B chunks)
    const __half* a_src = g_xh + (size_t)toks_s[tid >> 1] * DIM + (tid & 1) * 16;
    const uint32_t a_dst0 = smem_u32(As) + ((uint32_t)(tid >> 1) * AS_H + (tid & 1) * 16) * 2;
    // B: thread owns d-row (tid>>3), 4x 16B chunks at n = (tid&7)*8 + j*64
    const __half* b_src = g_w1h + (size_t)e * DIM * HID + (size_t)(tid >> 3) * HID
                        + nbase + (tid & 7) * 8;
    const uint32_t b_dst0 = smem_u32(Bs) + ((uint32_t)(tid >> 3) * BS_H + (tid & 7) * 8) * 2;

    // ---- ldmatrix base addresses (lane-dependent) ----
    const uint32_t a_lm = smem_u32(As)
        + (((uint32_t)(wy * 64 + (lane & 15)) * AS_H) + (uint32_t)(lane >> 4) * 8) * 2;
    const uint32_t b_lm = smem_u32(Bs)
        + (((uint32_t)(lane & 15) * BS_H) + (uint32_t)(wx * 64) + (uint32_t)(lane >> 4) * 8) * 2;

    float sacc[4][2];
#pragma unroll
    for (int mi = 0; mi < 4; mi++) { sacc[mi][0] = 0.f; sacc[mi][1] = 0.f; }

    float C[4][8][4];
#pragma unroll
    for (int mi = 0; mi < 4; mi++)
#pragma unroll
        for (int ni = 0; ni < 8; ni++)
#pragma unroll
            for (int q = 0; q < 4; q++) C[mi][ni][q] = 0.f;

    // tile j (0..63): hc = j>>5 (H-chunk of 256), kt = j&31 (d-step of 32), buf j%3
#define LOAD_TILE(j) do {                                                         \
        const int   _kt = (j) & 31;                                               \
        const int   _hc = (j) >> 5;                                               \
        const int   _bf = (j) % 3;                                                \
        const __half* _as = a_src + _kt * 32;                                     \
        const __half* _bs = b_src + (size_t)_kt * (32 * HID) + _hc * 256;         \
        uint32_t _ad = a_dst0 + (uint32_t)_bf * A_TILE_B;                         \
        uint32_t _bd = b_dst0 + (uint32_t)_bf * B_TILE_B;                         \
        CP_ASYNC16(_ad,      _as);                                                \
        CP_ASYNC16(_ad + 16, _as + 8);                                            \
        CP_ASYNC16(_bd,       _bs);                                               \
        CP_ASYNC16(_bd + 128, _bs + 64);                                          \
        CP_ASYNC16(_bd + 256, _bs + 128);                                         \
        CP_ASYNC16(_bd + 384, _bs + 192);                                         \
    } while (0)

    LOAD_TILE(0); CP_COMMIT();
    LOAD_TILE(1); CP_COMMIT();

    for (int it = 0; it < 64; it++) {
        CP_WAIT(1);
        __syncthreads();
        if (it < 62) LOAD_TILE(it + 2);
        CP_COMMIT();

        const uint32_t abuf = a_lm + (uint32_t)(it % 3) * A_TILE_B;
        const uint32_t bbuf = b_lm + (uint32_t)(it % 3) * B_TILE_B;
#pragma unroll
        for (int s = 0; s < 2; s++) {
            uint32_t af[4][4];
#pragma unroll
            for (int mi = 0; mi < 4; mi++)
                LDSM4(af[mi], abuf + (uint32_t)(mi * 16 * AS_H + s * 16) * 2);
            uint32_t bf[4][4];
#pragma unroll
            for (int p = 0; p < 4; p++)
                LDSM4T(bf[p], bbuf + (uint32_t)(s * 16 * BS_H + p * 16) * 2);
#pragma unroll
            for (int mi = 0; mi < 4; mi++)
#pragma unroll
                for (int p = 0; p < 4; p++) {
                    mma_f16(C[mi][2 * p],     af[mi], &bf[p][0]);
                    mma_f16(C[mi][2 * p + 1], af[mi], &bf[p][2]);
                }
        }

        if ((it & 31) == 31) {
            // fused epilogue for H-chunk (it>>5): relu(+b1) dot W2, reset C
            const int hb = (it >> 5) * 256;
#pragma unroll
            for (int mi = 0; mi < 4; mi++) {
#pragma unroll
                for (int ni = 0; ni < 8; ni++) {
                    const int nl = hb + wx * 64 + ni * 8 + 2 * c_;
                    float2 bb = *(const float2*)&b1s[nl];
                    float2 ww = *(const float2*)&w2s[nl];
                    sacc[mi][0] += fmaxf(C[mi][ni][0] + bb.x, 0.f) * ww.x
                                 + fmaxf(C[mi][ni][1] + bb.y, 0.f) * ww.y;
                    sacc[mi][1] += fmaxf(C[mi][ni][2] + bb.x, 0.f) * ww.x
                                 + fmaxf(C[mi][ni][3] + bb.y, 0.f) * ww.y;
                    C[mi][ni][0] = 0.f; C[mi][ni][1] = 0.f;
                    C[mi][ni][2] = 0.f; C[mi][ni][3] = 0.f;
                }
            }
        }
    }

    // ---- reduce: fold 4 c-lanes (shfl), then 4 warp columns (smem) ----
#pragma unroll
    for (int mi = 0; mi < 4; mi++)
#pragma unroll
        for (int j = 0; j < 2; j++) {
            float v = sacc[mi][j];
            v += __shfl_xor_sync(0xffffffffu, v, 1);
            v += __shfl_xor_sync(0xffffffffu, v, 2);
            sacc[mi][j] = v;
        }
    __syncthreads();
    if (c_ == 0) {
#pragma unroll
        for (int mi = 0; mi < 4; mi++) {
            red_s[(wy * 64 + mi * 16 + r_) * 4 + wx]     = sacc[mi][0];
            red_s[(wy * 64 + mi * 16 + r_ + 8) * 4 + wx] = sacc[mi][1];
        }
    }
    __syncthreads();

    if (tid < 128) {
        float tot = red_s[tid * 4] + red_s[tid * 4 + 1]
                  + red_s[tid * 4 + 2] + red_s[tid * 4 + 3];
        int idx = tbase + tid;
        if (idx < cnt) {
            if (slice == 0) tot += b2[e];
            atomicAdd(out + toks_s[tid], gts_s[tid] * tot);
        }
    }
}

// ---------------- launch ----------------
extern "C" void kernel_launch(void* const* d_in, const int* in_sizes, int n_in,
                              void* d_out, int out_size) {
    const float* x  = (const float*)d_in[0];
    const float* Wn = (const float*)d_in[3];
    const float* bn = (const float*)d_in[4];
    const float* W1 = (const float*)d_in[5];
    const float* b1 = (const float*)d_in[6];
    const float* W2 = (const float*)d_in[7];
    const float* b2 = (const float*)d_in[8];
    float* out = (float*)d_out;

    __half* xh;  cudaGetSymbolAddress((void**)&xh,  g_xh);
    __half* w1h; cudaGetSymbolAddress((void**)&w1h, g_w1h);

    cudaFuncSetAttribute(moe_mma_kernel,
                         cudaFuncAttributeMaxDynamicSharedMemorySize, MOE_SMEM_BYTES);

    zero_counts_kernel<<<1, 32>>>();
    router_kernel<<<N_TOK / 128, 256>>>(x, Wn, bn, out);
    to_half_kernel<<<(N_TOK * DIM / 4) / 256, 256>>>((const float4*)x, (__half2*)xh);
    to_half_kernel<<<((size_t)NEXP * DIM * HID / 4) / 256, 256>>>((const float4*)W1, (__half2*)w1h);
    moe_mma_kernel<<<dim3(128, NEXP, 8), 256, MOE_SMEM_BYTES>>>(b1, W2, b2, out);
}

// round 8
// speedup vs baseline: 10.1780x; 1.0942x over previous
#include <cuda_runtime.h>
#include <cuda_fp16.h>
#include <cstdint>

#define N_TOK 16384
#define DIM   1024
#define NEXP  16
#define HID   4096

// ---------------- device scratch (no allocations allowed) ----------------
__device__ int    g_counts[NEXP];
__device__ int    g_perm [NEXP * N_TOK];
__device__ float  g_gatev[NEXP * N_TOK];
__device__ __half g_xh [(size_t)N_TOK * DIM];          // x  rounded to fp16
__device__ __half g_w1h[(size_t)NEXP * DIM * HID];     // W1 rounded to fp16

// ---------------- helpers ----------------
__device__ __forceinline__ uint32_t smem_u32(const void* p) {
    uint32_t a;
    asm("{ .reg .u64 t; cvta.to.shared.u64 t, %1; cvt.u32.u64 %0, t; }" : "=r"(a) : "l"(p));
    return a;
}
#define CP_ASYNC16(dst, src) \
    asm volatile("cp.async.cg.shared.global [%0], [%1], 16;" :: "r"(dst), "l"(src) : "memory")
#define CP_COMMIT() asm volatile("cp.async.commit_group;" ::: "memory")
#define CP_WAIT(n)  asm volatile("cp.async.wait_group %0;" :: "n"(n) : "memory")

#define LDSM4(r, a) \
    asm volatile("ldmatrix.sync.aligned.m8n8.x4.shared.b16 {%0,%1,%2,%3}, [%4];" \
        : "=r"((r)[0]), "=r"((r)[1]), "=r"((r)[2]), "=r"((r)[3]) : "r"(a))
#define LDSM4T(r, a) \
    asm volatile("ldmatrix.sync.aligned.m8n8.x4.trans.shared.b16 {%0,%1,%2,%3}, [%4];" \
        : "=r"((r)[0]), "=r"((r)[1]), "=r"((r)[2]), "=r"((r)[3]) : "r"(a))

__device__ __forceinline__ void mma_f16(float* c, const uint32_t* a, const uint32_t* b) {
    asm volatile(
        "mma.sync.aligned.m16n8k16.row.col.f32.f16.f16.f32 "
        "{%0,%1,%2,%3}, {%4,%5,%6,%7}, {%8,%9}, {%0,%1,%2,%3};"
        : "+f"(c[0]), "+f"(c[1]), "+f"(c[2]), "+f"(c[3])
        : "r"(a[0]), "r"(a[1]), "r"(a[2]), "r"(a[3]), "r"(b[0]), "r"(b[1]));
}

// ---------------- kernel 0: zero counts ----------------
__global__ void zero_counts_kernel() {
    if (threadIdx.x < NEXP) g_counts[threadIdx.x] = 0;
}

// ---------------- kernel 1: fp16-round a buffer ----------------
__global__ __launch_bounds__(256) void to_half_kernel(const float4* __restrict__ src,
                                                      __half2* __restrict__ dst) {
    size_t i = (size_t)blockIdx.x * 256 + threadIdx.x;
    float4 v = src[i];
    dst[2 * i]     = __floats2half2_rn(v.x, v.y);
    dst[2 * i + 1] = __floats2half2_rn(v.z, v.w);
}

// ---------------- kernel 2: router (fp32 exact), 64 tokens/CTA ----------------
__global__ __launch_bounds__(256) void router_kernel(
    const float* __restrict__ x,
    const float* __restrict__ Wn,
    const float* __restrict__ bn,
    float* __restrict__ out)
{
    __shared__ float Xs[32][65];
    __shared__ float Ws[32][16];

    const int tid  = threadIdx.x;
    const int tx   = tid & 15;      // expert lane
    const int g    = tid >> 4;      // token sub-group 0..15
    const int tok0 = blockIdx.x * 64;

    float acc[4];
#pragma unroll
    for (int i = 0; i < 4; i++) acc[i] = 0.f;

    for (int dk = 0; dk < DIM; dk += 32) {
#pragma unroll
        for (int p = 0; p < 2; p++) {
            int t  = (tid >> 3) + p * 32;
            int d4 = (tid & 7) * 4;
            float4 v = *(const float4*)(x + (size_t)(tok0 + t) * DIM + dk + d4);
            Xs[d4 + 0][t] = v.x;
            Xs[d4 + 1][t] = v.y;
            Xs[d4 + 2][t] = v.z;
            Xs[d4 + 3][t] = v.w;
        }
        {
            int idx = tid * 2;
            int d = idx >> 4, ee = idx & 15;
            float2 w = *(const float2*)(Wn + (size_t)(dk + d) * NEXP + ee);
            Ws[d][ee]     = w.x;
            Ws[d][ee + 1] = w.y;
        }
        __syncthreads();
#pragma unroll
        for (int kk = 0; kk < 32; kk++) {
            float wv = Ws[kk][tx];
#pragma unroll
            for (int i = 0; i < 4; i++)
                acc[i] += Xs[kk][g + 16 * i] * wv;
        }
        __syncthreads();
    }

    const float bb = bn[tx];
#pragma unroll
    for (int i = 0; i < 4; i++) {
        float v0 = acc[i] + bb;
        int   i0 = tx;
        float v1 = -3.4e38f;
        int   i1 = NEXP;
#pragma unroll
        for (int off = 8; off >= 1; off >>= 1) {
            float ov0 = __shfl_xor_sync(0xffffffffu, v0, off);
            int   oi0 = __shfl_xor_sync(0xffffffffu, i0, off);
            float ov1 = __shfl_xor_sync(0xffffffffu, v1, off);
            int   oi1 = __shfl_xor_sync(0xffffffffu, i1, off);
            bool other_first = (ov0 > v0) || (ov0 == v0 && oi0 < i0);
            float n0, n1; int m0, m1;
            if (other_first) {
                n0 = ov0; m0 = oi0;
                if (v0 > ov1 || (v0 == ov1 && i0 < oi1)) { n1 = v0;  m1 = i0;  }
                else                                     { n1 = ov1; m1 = oi1; }
            } else {
                n0 = v0; m0 = i0;
                if (ov0 > v1 || (ov0 == v1 && oi0 < i1)) { n1 = ov0; m1 = oi0; }
                else                                     { n1 = v1;  m1 = i1;  }
            }
            v0 = n0; i0 = m0; v1 = n1; i1 = m1;
        }
        if (tx == 0) {
            int token = tok0 + g + 16 * i;
            float e1  = __expf(v1 - v0);
            float inv = 1.f / (1.f + e1);
            int p0 = atomicAdd(&g_counts[i0], 1);
            g_perm [i0 * N_TOK + p0] = token;
            g_gatev[i0 * N_TOK + p0] = inv;
            int p1 = atomicAdd(&g_counts[i1], 1);
            g_perm [i1 * N_TOK + p1] = token;
            g_gatev[i1 * N_TOK + p1] = e1 * inv;
            out[token] = 0.f;
        }
    }
}

// ---------------- kernel 3: fp16 mma expert GEMM, H-sliced ----------------
// CTA = (128-token tile, expert, H-slice of 512). 8 warps 2x4, warp tile 64x64.
// 64 tiles = 2 H-chunks(256) x 32 K-steps(32). 4-stage cp.async pipeline,
// ONE wait+__syncthreads per 2 tiles. ldmatrix frags. Fused relu(+b1)*W2.
#define AS_H 40                 // A smem row stride in halfs (32 + 8 pad)
#define BS_H 264                // B smem row stride in halfs (256 + 8 pad)
#define A_TILE_B (128 * AS_H * 2)     // 10240 bytes per A buffer
#define B_TILE_B (32 * BS_H * 2)      // 16896 bytes per B buffer
#define SM_B1_B   (4 * A_TILE_B + 4 * B_TILE_B)   // 108544
#define SM_W2_B   (SM_B1_B + 2048)
#define SM_TOK_B  (SM_W2_B + 2048)
#define SM_GTS_B  (SM_TOK_B + 512)
#define SM_RED_B  (SM_GTS_B + 512)
#define MOE_SMEM_BYTES (SM_RED_B + 2048)

__global__ __launch_bounds__(256, 1) void moe_mma_kernel(
    const float* __restrict__ b1,
    const float* __restrict__ W2,
    const float* __restrict__ b2,
    float* __restrict__ out)
{
    const int e     = blockIdx.y;
    const int cnt   = g_counts[e];
    const int tbase = blockIdx.x * 128;
    if (tbase >= cnt) return;
    const int slice = blockIdx.z;           // 0..7, 512 H cols each

    extern __shared__ char sm[];
    __half* As    = (__half*)sm;
    __half* Bs    = (__half*)(sm + 4 * A_TILE_B);
    float* b1s    = (float*)(sm + SM_B1_B);
    float* w2s    = (float*)(sm + SM_W2_B);
    int*   toks_s = (int*)  (sm + SM_TOK_B);
    float* gts_s  = (float*)(sm + SM_GTS_B);
    float* red_s  = (float*)(sm + SM_RED_B);   // [128][4]

    const int tid  = threadIdx.x;
    const int wid  = tid >> 5;
    const int lane = tid & 31;
    const int wy   = wid >> 2;              // 0..1 (m block 64)
    const int wx   = wid & 3;               // 0..3 (n block 64)
    const int r_   = lane >> 2;             // 0..7
    const int c_   = lane & 3;              // 0..3

    const int nbase = slice * 512;
    if (tid < 128) {
        int idx = tbase + tid;
        int t = 0; float gv = 0.f;
        if (idx < cnt) { t = g_perm[e * N_TOK + idx]; gv = g_gatev[e * N_TOK + idx]; }
        toks_s[tid] = t;
        gts_s[tid]  = gv;
    }
    {
        const float* b1e = b1 + (size_t)e * HID + nbase;
        const float* w2e = W2 + (size_t)e * HID + nbase;
        b1s[tid]       = b1e[tid];
        b1s[tid + 256] = b1e[tid + 256];
        w2s[tid]       = w2e[tid];
        w2s[tid + 256] = w2e[tid + 256];
    }
    __syncthreads();

    // ---- cp.async loader setup ----
    const __half* a_src = g_xh + (size_t)toks_s[tid >> 1] * DIM + (tid & 1) * 16;
    const uint32_t a_dst0 = smem_u32(As) + ((uint32_t)(tid >> 1) * AS_H + (tid & 1) * 16) * 2;
    const __half* b_src = g_w1h + (size_t)e * DIM * HID + (size_t)(tid >> 3) * HID
                        + nbase + (tid & 7) * 8;
    const uint32_t b_dst0 = smem_u32(Bs) + ((uint32_t)(tid >> 3) * BS_H + (tid & 7) * 8) * 2;

    // ---- ldmatrix base addresses (lane-dependent) ----
    const uint32_t a_lm = smem_u32(As)
        + (((uint32_t)(wy * 64 + (lane & 15)) * AS_H) + (uint32_t)(lane >> 4) * 8) * 2;
    const uint32_t b_lm = smem_u32(Bs)
        + (((uint32_t)(lane & 15) * BS_H) + (uint32_t)(wx * 64) + (uint32_t)(lane >> 4) * 8) * 2;

    float sacc[4][2];
#pragma unroll
    for (int mi = 0; mi < 4; mi++) { sacc[mi][0] = 0.f; sacc[mi][1] = 0.f; }

    float C[4][8][4];
#pragma unroll
    for (int mi = 0; mi < 4; mi++)
#pragma unroll
        for (int ni = 0; ni < 8; ni++)
#pragma unroll
            for (int q = 0; q < 4; q++) C[mi][ni][q] = 0.f;

    // tile j (0..63): hc = j>>5 (H-chunk of 256), kt = j&31 (d-step of 32), buf j%4
#define LOAD_TILE(j) do {                                                         \
        const int   _kt = (j) & 31;                                               \
        const int   _hc = (j) >> 5;                                               \
        const int   _bf = (j) & 3;                                                \
        const __half* _as = a_src + _kt * 32;                                     \
        const __half* _bs = b_src + (size_t)_kt * (32 * HID) + _hc * 256;         \
        uint32_t _ad = a_dst0 + (uint32_t)_bf * A_TILE_B;                         \
        uint32_t _bd = b_dst0 + (uint32_t)_bf * B_TILE_B;                         \
        CP_ASYNC16(_ad,      _as);                                                \
        CP_ASYNC16(_ad + 16, _as + 8);                                            \
        CP_ASYNC16(_bd,       _bs);                                               \
        CP_ASYNC16(_bd + 128, _bs + 64);                                          \
        CP_ASYNC16(_bd + 256, _bs + 128);                                         \
        CP_ASYNC16(_bd + 384, _bs + 192);                                         \
    } while (0)

    // compute one tile from its buffer; epilogue folded in at H-chunk boundary
#define COMPUTE_TILE(it) do {                                                     \
        const uint32_t abuf = a_lm + (uint32_t)((it) & 3) * A_TILE_B;             \
        const uint32_t bbuf = b_lm + (uint32_t)((it) & 3) * B_TILE_B;             \
        _Pragma("unroll")                                                         \
        for (int s = 0; s < 2; s++) {                                             \
            uint32_t af[4][4];                                                    \
            _Pragma("unroll")                                                     \
            for (int mi = 0; mi < 4; mi++)                                        \
                LDSM4(af[mi], abuf + (uint32_t)(mi * 16 * AS_H + s * 16) * 2);    \
            uint32_t bf[4][4];                                                    \
            _Pragma("unroll")                                                     \
            for (int p = 0; p < 4; p++)                                           \
                LDSM4T(bf[p], bbuf + (uint32_t)(s * 16 * BS_H + p * 16) * 2);     \
            _Pragma("unroll")                                                     \
            for (int mi = 0; mi < 4; mi++)                                        \
                _Pragma("unroll")                                                 \
                for (int p = 0; p < 4; p++) {                                     \
                    mma_f16(C[mi][2 * p],     af[mi], &bf[p][0]);                 \
                    mma_f16(C[mi][2 * p + 1], af[mi], &bf[p][2]);                 \
                }                                                                 \
        }                                                                         \
        if (((it) & 31) == 31) {                                                  \
            const int hb = ((it) >> 5) * 256;                                     \
            _Pragma("unroll")                                                     \
            for (int mi = 0; mi < 4; mi++) {                                      \
                _Pragma("unroll")                                                 \
                for (int ni = 0; ni < 8; ni++) {                                  \
                    const int nl = hb + wx * 64 + ni * 8 + 2 * c_;                \
                    float2 bb = *(const float2*)&b1s[nl];                         \
                    float2 ww = *(const float2*)&w2s[nl];                         \
                    sacc[mi][0] += fmaxf(C[mi][ni][0] + bb.x, 0.f) * ww.x         \
                                 + fmaxf(C[mi][ni][1] + bb.y, 0.f) * ww.y;        \
                    sacc[mi][1] += fmaxf(C[mi][ni][2] + bb.x, 0.f) * ww.x         \
                                 + fmaxf(C[mi][ni][3] + bb.y, 0.f) * ww.y;        \
                    C[mi][ni][0] = 0.f; C[mi][ni][1] = 0.f;                       \
                    C[mi][ni][2] = 0.f; C[mi][ni][3] = 0.f;                       \
                }                                                                 \
            }                                                                     \
        }                                                                         \
    } while (0)

    // prologue: tiles 0,1 as one group
    LOAD_TILE(0); LOAD_TILE(1); CP_COMMIT();

    for (int j = 0; j < 32; j++) {
        const int i0 = 2 * j;
        CP_WAIT(0);            // drain previous step's group (tiles i0, i0+1)
        __syncthreads();
        if (i0 + 2 < 64) {
            LOAD_TILE(i0 + 2);
            LOAD_TILE(i0 + 3);
        }
        CP_COMMIT();
        COMPUTE_TILE(i0);
        COMPUTE_TILE(i0 + 1);
    }

    // ---- reduce: fold 4 c-lanes (shfl), then 4 warp columns (smem) ----
#pragma unroll
    for (int mi = 0; mi < 4; mi++)
#pragma unroll
        for (int j = 0; j < 2; j++) {
            float v = sacc[mi][j];
            v += __shfl_xor_sync(0xffffffffu, v, 1);
            v += __shfl_xor_sync(0xffffffffu, v, 2);
            sacc[mi][j] = v;
        }
    __syncthreads();
    if (c_ == 0) {
#pragma unroll
        for (int mi = 0; mi < 4; mi++) {
            red_s[(wy * 64 + mi * 16 + r_) * 4 + wx]     = sacc[mi][0];
            red_s[(wy * 64 + mi * 16 + r_ + 8) * 4 + wx] = sacc[mi][1];
        }
    }
    __syncthreads();

    if (tid < 128) {
        float tot = red_s[tid * 4] + red_s[tid * 4 + 1]
                  + red_s[tid * 4 + 2] + red_s[tid * 4 + 3];
        int idx = tbase + tid;
        if (idx < cnt) {
            if (slice == 0) tot += b2[e];
            atomicAdd(out + toks_s[tid], gts_s[tid] * tot);
        }
    }
}

// ---------------- launch ----------------
extern "C" void kernel_launch(void* const* d_in, const int* in_sizes, int n_in,
                              void* d_out, int out_size) {
    const float* x  = (const float*)d_in[0];
    const float* Wn = (const float*)d_in[3];
    const float* bn = (const float*)d_in[4];
    const float* W1 = (const float*)d_in[5];
    const float* b1 = (const float*)d_in[6];
    const float* W2 = (const float*)d_in[7];
    const float* b2 = (const float*)d_in[8];
    float* out = (float*)d_out;

    __half* xh;  cudaGetSymbolAddress((void**)&xh,  g_xh);
    __half* w1h; cudaGetSymbolAddress((void**)&w1h, g_w1h);

    // one-time resource setup (host-side only; identical device work every call)
    static cudaStream_t s2 = nullptr;
    static cudaEvent_t  evF = nullptr, evJ = nullptr;
    if (s2 == nullptr) {
        cudaStreamCreateWithFlags(&s2, cudaStreamNonBlocking);
        cudaEventCreateWithFlags(&evF, cudaEventDisableTiming);
        cudaEventCreateWithFlags(&evJ, cudaEventDisableTiming);
        cudaFuncSetAttribute(moe_mma_kernel,
                             cudaFuncAttributeMaxDynamicSharedMemorySize, MOE_SMEM_BYTES);
    }

    // fork: conversions on s2 run concurrently with zero+router on the main stream
    cudaEventRecord(evF, 0);
    cudaStreamWaitEvent(s2, evF, 0);
    to_half_kernel<<<(N_TOK * DIM / 4) / 256, 256, 0, s2>>>((const float4*)x, (__half2*)xh);
    to_half_kernel<<<((size_t)NEXP * DIM * HID / 4) / 256, 256, 0, s2>>>(
        (const float4*)W1, (__half2*)w1h);

    zero_counts_kernel<<<1, 32>>>();
    router_kernel<<<N_TOK / 64, 256>>>(x, Wn, bn, out);

    // join: moe needs router output AND both conversions
    cudaEventRecord(evJ, s2);
    cudaStreamWaitEvent(0, evJ, 0);
    moe_mma_kernel<<<dim3(128, NEXP, 8), 256, MOE_SMEM_BYTES>>>(b1, W2, b2, out);
}